// round 2
// baseline (speedup 1.0000x reference)
#include <cuda_runtime.h>
#include <math.h>

#define B_ 512
#define N_ 128
#define E_ 256
#define H_ 8
#define D_ 32
#define SCALE_ 0.17677669529663687f  /* 1/sqrt(32) */
#define NEGV  (-1000000000.0f)
#define CLIPV 10.0f
#define KROW  260                    /* padded smem row for k (bank-conflict-free) */

// ---------------- scratch (device globals; no allocation) ----------------
__device__ float g_qkv[(size_t)B_ * N_ * 768];  // k | v | logit_k   (192 MB)
__device__ float g_Qc [(size_t)B_ * N_ * E_];   // X @ Wstep_bot     (64 MB)
__device__ float g_M  [(size_t)B_ * N_ * E_];   // logit_k @ Wmlp^T  (64 MB)
__device__ float g_bdot[B_ * N_];
__device__ float g_ge [B_ * E_];                // graph_emb
__device__ float g_qf [B_ * E_];                // q_first

// ---------------- graph_emb = mean over nodes ----------------
__global__ void mean_k(const float* __restrict__ ne) {
    int b = blockIdx.x, e = threadIdx.x;
    const float* p = ne + (size_t)b * N_ * E_ + e;
    float s = 0.f;
#pragma unroll 8
    for (int n = 0; n < N_; n++) s += p[(size_t)n * E_];
    g_ge[b * E_ + e] = s * (1.0f / N_);
}

// ---------------- q_first = ge@Wfix + first@Wstep_top + bfix + bstep ----------------
__global__ void qfirst_k(const float* __restrict__ ne,
                         const float* __restrict__ Wfix, const float* __restrict__ bfix,
                         const float* __restrict__ Wstep, const float* __restrict__ bstep) {
    __shared__ float ge_s[E_], fi_s[E_];
    int b = blockIdx.x, t = threadIdx.x;
    ge_s[t] = g_ge[b * E_ + t];
    fi_s[t] = ne[(size_t)b * N_ * E_ + t];  // node 0 = first
    __syncthreads();
    float acc = bfix[t] + bstep[t];
#pragma unroll 4
    for (int f = 0; f < E_; f++) {
        acc = fmaf(ge_s[f], Wfix[f * E_ + t], acc);
        acc = fmaf(fi_s[f], Wstep[f * E_ + t], acc);
    }
    g_qf[b * E_ + t] = acc;
}

// ---------------- generic fp32 GEMM: C = A(MxK)*B(KxN) [+bias] ----------------
// BM=BN=128, BK=8, 256 threads, 8x8 microtile. Dims assumed exact multiples.
template <int TRANSB>
__global__ void __launch_bounds__(256) sgemm_k(
    const float* __restrict__ A, const float* __restrict__ Bm,
    const float* __restrict__ bias, float* __restrict__ C,
    int K, int lda, int ldb, int ldc) {
    __shared__ float As[8][128];
    __shared__ float Bs[8][128];
    int tid = threadIdx.x;
    int tx = tid & 15, ty = tid >> 4;
    int rowBase = blockIdx.y * 128;
    int colBase = blockIdx.x * 128;

    float acc[8][8];
#pragma unroll
    for (int i = 0; i < 8; i++)
#pragma unroll
        for (int j = 0; j < 8; j++) acc[i][j] = 0.f;

    int aR = tid >> 1;            // 0..127
    int aC = (tid & 1) * 4;       // 0 or 4
    int bK_n = tid >> 5;          // 0..7   (normal B)
    int bC_n = (tid & 31) * 4;
    int bCol_t = tid & 127;       // trans B
    int bK_t = (tid >> 7) * 4;    // 0 or 4

    for (int kt = 0; kt < K; kt += 8) {
        float4 av = *(const float4*)(A + (size_t)(rowBase + aR) * lda + kt + aC);
        As[aC + 0][aR] = av.x; As[aC + 1][aR] = av.y;
        As[aC + 2][aR] = av.z; As[aC + 3][aR] = av.w;
        if (!TRANSB) {
            float4 bv = *(const float4*)(Bm + (size_t)(kt + bK_n) * ldb + colBase + bC_n);
            *(float4*)&Bs[bK_n][bC_n] = bv;
        } else {
            float4 bv = *(const float4*)(Bm + (size_t)(colBase + bCol_t) * ldb + kt + bK_t);
            Bs[bK_t + 0][bCol_t] = bv.x; Bs[bK_t + 1][bCol_t] = bv.y;
            Bs[bK_t + 2][bCol_t] = bv.z; Bs[bK_t + 3][bCol_t] = bv.w;
        }
        __syncthreads();
#pragma unroll
        for (int kk = 0; kk < 8; kk++) {
            float ra[8], rb[8];
            *(float4*)&ra[0] = *(const float4*)&As[kk][ty * 8];
            *(float4*)&ra[4] = *(const float4*)&As[kk][ty * 8 + 4];
            *(float4*)&rb[0] = *(const float4*)&Bs[kk][tx * 8];
            *(float4*)&rb[4] = *(const float4*)&Bs[kk][tx * 8 + 4];
#pragma unroll
            for (int i = 0; i < 8; i++)
#pragma unroll
                for (int j = 0; j < 8; j++) acc[i][j] = fmaf(ra[i], rb[j], acc[i][j]);
        }
        __syncthreads();
    }
#pragma unroll
    for (int i = 0; i < 8; i++) {
        int r = rowBase + ty * 8 + i;
#pragma unroll
        for (int j = 0; j < 8; j += 4) {
            int c = colBase + tx * 8 + j;
            float4 v;
            v.x = acc[i][j]; v.y = acc[i][j + 1]; v.z = acc[i][j + 2]; v.w = acc[i][j + 3];
            if (bias) { v.x += bias[c]; v.y += bias[c + 1]; v.z += bias[c + 2]; v.w += bias[c + 3]; }
            *(float4*)(C + (size_t)r * ldc + c) = v;
        }
    }
}

// ---------------- bdot[row] = SCALE * (bmlp . logit_k[row]) ----------------
__global__ void bdot_k(const float* __restrict__ bmlp) {
    int w = threadIdx.x >> 5, l = threadIdx.x & 31;
    int row = blockIdx.x * 8 + w;  // 0..65535
    const float* lk = g_qkv + (size_t)row * 768 + 512;
    float acc = 0.f;
#pragma unroll
    for (int j = 0; j < 8; j++) acc = fmaf(bmlp[l + 32 * j], lk[l + 32 * j], acc);
#pragma unroll
    for (int o = 16; o; o >>= 1) acc += __shfl_xor_sync(0xffffffffu, acc, o);
    if (l == 0) g_bdot[row] = acc * SCALE_;
}

// ---------------- sequential greedy decode: 1 CTA per batch ----------------
__global__ void __launch_bounds__(256, 1) decode_k(float* __restrict__ out) {
    extern __shared__ float k_s[];  // [128][KROW]
    __shared__ float q_s[E_];
    __shared__ float qf_s[E_];
    __shared__ float ctx_s[E_];
    __shared__ float logits_s[N_];
    __shared__ int cur_s;
    __shared__ unsigned char vis_s[N_];

    int b = blockIdx.x, tid = threadIdx.x;
    int w = tid >> 5, l = tid & 31;

    // stage k[b] (qkv cols 0..255) into smem, padded rows
    const float* kbase = g_qkv + (size_t)b * N_ * 768;
    for (int idx = tid; idx < N_ * 64; idx += 256) {
        int n = idx >> 6, c = idx & 63;
        float4 v = *(const float4*)(kbase + (size_t)n * 768 + c * 4);
        *(float4*)&k_s[n * KROW + c * 4] = v;
    }
    qf_s[tid] = g_qf[b * E_ + tid];
    if (tid < N_) vis_s[tid] = (tid == 0) ? 1 : 0;
    if (tid == 0) cur_s = 0;
    __syncthreads();

    const float4* vbase4 = (const float4*)(g_qkv + (size_t)b * N_ * 768 + 256);  // row stride 192 f4
    const float4* Mbase4 = (const float4*)(g_M + (size_t)b * N_ * E_);
    const float* Qcb = g_Qc + (size_t)b * N_ * E_;
    const float* bd = g_bdot + b * N_;

    float lp = 0.f;

    for (int step = 0; step < N_ - 1; step++) {
        int cur = cur_s;
        // q = q_first + Qcand[cur]
        q_s[tid] = qf_s[tid] + Qcb[(size_t)cur * E_ + tid];
        __syncthreads();

        // ---- attention logits: warp w = head w; lane l owns n = l + 32j ----
        float a[4];
#pragma unroll
        for (int j = 0; j < 4; j++) {
            int n = l + 32 * j;
            float accs = 0.f;
#pragma unroll
            for (int jj = 0; jj < 8; jj++) {
                float4 kv = *(const float4*)&k_s[n * KROW + w * 32 + jj * 4];
                float4 qv = *(const float4*)&q_s[w * 32 + jj * 4];
                accs = fmaf(kv.x, qv.x, accs); accs = fmaf(kv.y, qv.y, accs);
                accs = fmaf(kv.z, qv.z, accs); accs = fmaf(kv.w, qv.w, accs);
            }
            accs *= SCALE_;
            if (vis_s[n]) accs = NEGV;
            a[j] = accs;
        }
        // per-head softmax (warp-local over 128 entries)
        float m = fmaxf(fmaxf(a[0], a[1]), fmaxf(a[2], a[3]));
#pragma unroll
        for (int o = 16; o; o >>= 1) m = fmaxf(m, __shfl_xor_sync(0xffffffffu, m, o));
        float ssum = 0.f;
#pragma unroll
        for (int j = 0; j < 4; j++) { a[j] = expf(a[j] - m); ssum += a[j]; }
#pragma unroll
        for (int o = 16; o; o >>= 1) ssum += __shfl_xor_sync(0xffffffffu, ssum, o);
        float inv = 1.0f / ssum;
#pragma unroll
        for (int j = 0; j < 4; j++) a[j] *= inv;

        // ---- ctx[w*32 + d] = sum_n attn[n] * v[n][w*32+d] ----
        int g = l >> 3, dsub = l & 7;  // lane groups over n mod 4; dsub -> 4 d's
        float4 c4 = make_float4(0.f, 0.f, 0.f, 0.f);
#pragma unroll
        for (int i = 0; i < 32; i++) {
            int n = g + 4 * i;
            float wgt = __shfl_sync(0xffffffffu, a[i >> 3], n & 31);
            float4 vv = vbase4[(size_t)n * 192 + w * 8 + dsub];
            c4.x = fmaf(wgt, vv.x, c4.x); c4.y = fmaf(wgt, vv.y, c4.y);
            c4.z = fmaf(wgt, vv.z, c4.z); c4.w = fmaf(wgt, vv.w, c4.w);
        }
        c4.x += __shfl_down_sync(0xffffffffu, c4.x, 16);
        c4.y += __shfl_down_sync(0xffffffffu, c4.y, 16);
        c4.z += __shfl_down_sync(0xffffffffu, c4.z, 16);
        c4.w += __shfl_down_sync(0xffffffffu, c4.w, 16);
        c4.x += __shfl_down_sync(0xffffffffu, c4.x, 8);
        c4.y += __shfl_down_sync(0xffffffffu, c4.y, 8);
        c4.z += __shfl_down_sync(0xffffffffu, c4.z, 8);
        c4.w += __shfl_down_sync(0xffffffffu, c4.w, 8);
        if (l < 8) *(float4*)&ctx_s[w * 32 + dsub * 4] = c4;
        __syncthreads();

        // ---- logits[n] = tanh(SCALE * ctx.M[n] + bdot[n]) * CLIP, masked ----
        float4 cA = *(const float4*)&ctx_s[l * 4];
        float4 cB = *(const float4*)&ctx_s[(l + 32) * 4];
#pragma unroll
        for (int ii = 0; ii < 16; ii++) {
            int n = w * 16 + ii;
            const float4* Mr = Mbase4 + (size_t)n * 64;
            float4 mA = Mr[l], mB = Mr[l + 32];
            float acc = cA.x * mA.x;
            acc = fmaf(cA.y, mA.y, acc); acc = fmaf(cA.z, mA.z, acc); acc = fmaf(cA.w, mA.w, acc);
            acc = fmaf(cB.x, mB.x, acc); acc = fmaf(cB.y, mB.y, acc);
            acc = fmaf(cB.z, mB.z, acc); acc = fmaf(cB.w, mB.w, acc);
#pragma unroll
            for (int o = 16; o; o >>= 1) acc += __shfl_xor_sync(0xffffffffu, acc, o);
            if (l == 0) {
                float lg = fmaf(SCALE_, acc, bd[n]);
                lg = tanhf(lg) * CLIPV;
                if (vis_s[n]) lg = NEGV;
                logits_s[n] = lg;
            }
        }
        __syncthreads();

        // ---- warp 0: argmax (first-index tie-break) + logsumexp + state update ----
        if (w == 0) {
            float lv[4];
            float bv = -3.0e38f; int bi = 0;
#pragma unroll
            for (int j = 0; j < 4; j++) {
                lv[j] = logits_s[l + 32 * j];
                if (lv[j] > bv) { bv = lv[j]; bi = l + 32 * j; }
            }
#pragma unroll
            for (int o = 16; o; o >>= 1) {
                float ov = __shfl_xor_sync(0xffffffffu, bv, o);
                int oi = __shfl_xor_sync(0xffffffffu, bi, o);
                if (ov > bv || (ov == bv && oi < bi)) { bv = ov; bi = oi; }
            }
            float es = 0.f;
#pragma unroll
            for (int j = 0; j < 4; j++) es += expf(lv[j] - bv);
#pragma unroll
            for (int o = 16; o; o >>= 1) es += __shfl_xor_sync(0xffffffffu, es, o);
            if (l == 0) {
                lp -= logf(es);  // chosen = logits[argmax] - lse = -log(sum exp(l - max))
                cur_s = bi;
                vis_s[bi] = 1;
            }
        }
        __syncthreads();
    }

    if (tid == 0) out[b] = lp;
}

// ---------------- host launch ----------------
extern "C" void kernel_launch(void* const* d_in, const int* in_sizes, int n_in,
                              void* d_out, int out_size) {
    const float* ne    = (const float*)d_in[0];
    const float* Wqkv  = (const float*)d_in[1];
    const float* bqkv  = (const float*)d_in[2];
    const float* Wfix  = (const float*)d_in[3];
    const float* bfix  = (const float*)d_in[4];
    const float* Wstep = (const float*)d_in[5];
    const float* bstep = (const float*)d_in[6];
    const float* Wmlp  = (const float*)d_in[7];
    const float* bmlp  = (const float*)d_in[8];
    float* out = (float*)d_out;

    float *p_qkv = nullptr, *p_Qc = nullptr, *p_M = nullptr;
    cudaGetSymbolAddress((void**)&p_qkv, g_qkv);
    cudaGetSymbolAddress((void**)&p_Qc, g_Qc);
    cudaGetSymbolAddress((void**)&p_M, g_M);

    size_t dec_smem = (size_t)N_ * KROW * sizeof(float);  // 133120
    cudaFuncSetAttribute(decode_k, cudaFuncAttributeMaxDynamicSharedMemorySize,
                         (int)dec_smem + 1024);

    mean_k<<<B_, E_>>>(ne);
    qfirst_k<<<B_, E_>>>(ne, Wfix, bfix, Wstep, bstep);

    // qkv = X @ Wqkv + bqkv   (65536 x 768 x 256)
    sgemm_k<0><<<dim3(768 / 128, (B_ * N_) / 128), 256>>>(ne, Wqkv, bqkv, p_qkv,
                                                          E_, E_, 768, 768);
    // Qcand = X @ Wstep[256:,:]   (65536 x 256 x 256)
    sgemm_k<0><<<dim3(E_ / 128, (B_ * N_) / 128), 256>>>(ne, Wstep + 256 * 256, nullptr,
                                                         p_Qc, E_, E_, E_, E_);
    // M = logit_k @ Wmlp^T   (65536 x 256 x 256)
    sgemm_k<1><<<dim3(E_ / 128, (B_ * N_) / 128), 256>>>(p_qkv + 512, Wmlp, nullptr,
                                                         p_M, E_, 768, E_, E_);
    bdot_k<<<(B_ * N_) / 8, 256>>>(bmlp);

    decode_k<<<B_, 256, dec_smem>>>(out);
}

// round 3
// speedup vs baseline: 1.0488x; 1.0488x over previous
#include <cuda_runtime.h>
#include <math.h>

#define B_ 512
#define N_ 128
#define E_ 256
#define H_ 8
#define D_ 32
#define SCALE_ 0.17677669529663687f  /* 1/sqrt(32) */
#define NEGV  (-1000000000.0f)
#define CLIPV 10.0f
#define KROW  260                    /* padded smem row for k (float4 conflict-free) */
#define MSU   33                     /* Ms row stride in float4 units (odd -> conflict-free) */

// ---------------- scratch (device globals; no allocation) ----------------
__device__ float g_qkv[(size_t)B_ * N_ * 768];  // k | v | logit_k
__device__ float g_Qc [(size_t)B_ * N_ * E_];   // X @ Wstep_bot
__device__ float g_M  [(size_t)B_ * N_ * E_];   // logit_k @ Wmlp^T
__device__ float g_bdot[B_ * N_];
__device__ float g_ge [B_ * E_];
__device__ float g_qf [B_ * E_];

// ---------------- graph_emb = mean over nodes ----------------
__global__ void mean_k(const float* __restrict__ ne) {
    int b = blockIdx.x, e = threadIdx.x;
    const float* p = ne + (size_t)b * N_ * E_ + e;
    float s = 0.f;
#pragma unroll 8
    for (int n = 0; n < N_; n++) s += p[(size_t)n * E_];
    g_ge[b * E_ + e] = s * (1.0f / N_);
}

// ---------------- q_first = ge@Wfix + first@Wstep_top + bfix + bstep ----------------
__global__ void qfirst_k(const float* __restrict__ ne,
                         const float* __restrict__ Wfix, const float* __restrict__ bfix,
                         const float* __restrict__ Wstep, const float* __restrict__ bstep) {
    __shared__ float ge_s[E_], fi_s[E_];
    int b = blockIdx.x, t = threadIdx.x;
    ge_s[t] = g_ge[b * E_ + t];
    fi_s[t] = ne[(size_t)b * N_ * E_ + t];
    __syncthreads();
    float acc = bfix[t] + bstep[t];
#pragma unroll 4
    for (int f = 0; f < E_; f++) {
        acc = fmaf(ge_s[f], Wfix[f * E_ + t], acc);
        acc = fmaf(fi_s[f], Wstep[f * E_ + t], acc);
    }
    g_qf[b * E_ + t] = acc;
}

// ---------------- generic fp32 GEMM: C = A(MxK)*B(KxN) [+bias] ----------------
template <int TRANSB>
__global__ void __launch_bounds__(256) sgemm_k(
    const float* __restrict__ A, const float* __restrict__ Bm,
    const float* __restrict__ bias, float* __restrict__ C,
    int K, int lda, int ldb, int ldc) {
    __shared__ float As[8][128];
    __shared__ float Bs[8][128];
    int tid = threadIdx.x;
    int tx = tid & 15, ty = tid >> 4;
    int rowBase = blockIdx.y * 128;
    int colBase = blockIdx.x * 128;

    float acc[8][8];
#pragma unroll
    for (int i = 0; i < 8; i++)
#pragma unroll
        for (int j = 0; j < 8; j++) acc[i][j] = 0.f;

    int aR = tid >> 1;
    int aC = (tid & 1) * 4;
    int bK_n = tid >> 5;
    int bC_n = (tid & 31) * 4;
    int bCol_t = tid & 127;
    int bK_t = (tid >> 7) * 4;

    for (int kt = 0; kt < K; kt += 8) {
        float4 av = *(const float4*)(A + (size_t)(rowBase + aR) * lda + kt + aC);
        As[aC + 0][aR] = av.x; As[aC + 1][aR] = av.y;
        As[aC + 2][aR] = av.z; As[aC + 3][aR] = av.w;
        if (!TRANSB) {
            float4 bv = *(const float4*)(Bm + (size_t)(kt + bK_n) * ldb + colBase + bC_n);
            *(float4*)&Bs[bK_n][bC_n] = bv;
        } else {
            float4 bv = *(const float4*)(Bm + (size_t)(colBase + bCol_t) * ldb + kt + bK_t);
            Bs[bK_t + 0][bCol_t] = bv.x; Bs[bK_t + 1][bCol_t] = bv.y;
            Bs[bK_t + 2][bCol_t] = bv.z; Bs[bK_t + 3][bCol_t] = bv.w;
        }
        __syncthreads();
#pragma unroll
        for (int kk = 0; kk < 8; kk++) {
            float ra[8], rb[8];
            *(float4*)&ra[0] = *(const float4*)&As[kk][ty * 8];
            *(float4*)&ra[4] = *(const float4*)&As[kk][ty * 8 + 4];
            *(float4*)&rb[0] = *(const float4*)&Bs[kk][tx * 8];
            *(float4*)&rb[4] = *(const float4*)&Bs[kk][tx * 8 + 4];
#pragma unroll
            for (int i = 0; i < 8; i++)
#pragma unroll
                for (int j = 0; j < 8; j++) acc[i][j] = fmaf(ra[i], rb[j], acc[i][j]);
        }
        __syncthreads();
    }
#pragma unroll
    for (int i = 0; i < 8; i++) {
        int r = rowBase + ty * 8 + i;
#pragma unroll
        for (int j = 0; j < 8; j += 4) {
            int c = colBase + tx * 8 + j;
            float4 v;
            v.x = acc[i][j]; v.y = acc[i][j + 1]; v.z = acc[i][j + 2]; v.w = acc[i][j + 3];
            if (bias) { v.x += bias[c]; v.y += bias[c + 1]; v.z += bias[c + 2]; v.w += bias[c + 3]; }
            *(float4*)(C + (size_t)r * ldc + c) = v;
        }
    }
}

// ---------------- bdot[row] = SCALE * (bmlp . logit_k[row]) ----------------
__global__ void bdot_k(const float* __restrict__ bmlp) {
    int w = threadIdx.x >> 5, l = threadIdx.x & 31;
    int row = blockIdx.x * 8 + w;
    const float* lk = g_qkv + (size_t)row * 768 + 512;
    float acc = 0.f;
#pragma unroll
    for (int j = 0; j < 8; j++) acc = fmaf(bmlp[l + 32 * j], lk[l + 32 * j], acc);
#pragma unroll
    for (int o = 16; o; o >>= 1) acc += __shfl_xor_sync(0xffffffffu, acc, o);
    if (l == 0) g_bdot[row] = acc * SCALE_;
}

// ---------------- sequential greedy decode: 1 CTA (512 thr) per batch ----------------
// smem: k fp32 (133 KB) + half of M (d 0..127, 67.6 KB). v lives in registers
// (64 floats/thread). Per-step L2 traffic: M-half (64 KB) + Qc row (1 KB).
__global__ void __launch_bounds__(512, 1) decode_k(float* __restrict__ out) {
    extern __shared__ float dyn_s[];
    float* k_s = dyn_s;                              // [128][KROW]
    float4* Ms4 = (float4*)(dyn_s + N_ * KROW);      // [128][MSU] (32 units used)

    __shared__ float q_s[E_], qf_s[E_], ctx_s[E_];
    __shared__ float attn_s[H_ * 130];               // padded: idx = h*130 + n + (n>=64)
    __shared__ float lp_part[4][N_];
    __shared__ float logits_s[N_], bd_s[N_];
    __shared__ int cur_s;
    __shared__ unsigned char vis_s[N_];

    int b = blockIdx.x, tid = threadIdx.x;
    int w = tid >> 5, l = tid & 31;

    const float* kbase = g_qkv + (size_t)b * N_ * 768;
    const float4* Mb4 = (const float4*)(g_M + (size_t)b * N_ * E_);
    const float* Qcb = g_Qc + (size_t)b * N_ * E_;

    // ---- stage k into smem ----
    for (int idx = tid; idx < N_ * 64; idx += 512) {
        int n = idx >> 6, c = idx & 63;
        float4 v = *(const float4*)(kbase + (size_t)n * 768 + c * 4);
        *(float4*)&k_s[n * KROW + c * 4] = v;
    }
    // ---- stage M lower half (d 0..127) into smem ----
    for (int idx = tid; idx < N_ * 32; idx += 512) {
        int n = idx >> 5, u = idx & 31;
        Ms4[n * MSU + u] = Mb4[n * 64 + u];
    }
    // ---- stage v into registers: thread t holds v[nh*64+i][d], d=t>>1, nh=t&1 ----
    float v_reg[64];
    {
        int d = tid >> 1, nh = tid & 1;
        const float* vb = kbase + 256 + d + (size_t)nh * 64 * 768;
#pragma unroll
        for (int i = 0; i < 64; i++) v_reg[i] = vb[(size_t)i * 768];
    }
    if (tid < E_) qf_s[tid] = g_qf[b * E_ + tid];
    if (tid < N_) {
        bd_s[tid] = g_bdot[b * N_ + tid];
        vis_s[tid] = (tid == 0) ? 1 : 0;
    }
    if (tid == 0) cur_s = 0;
    __syncthreads();

    int nL = tid & 127, pL = tid >> 7;               // logits mapping (warp-uniform p)
    const float4* MrowL2 = Mb4 + nL * 64 + pL * 16;  // valid for pL>=2 (d-units 32..63)

    float lp = 0.f;

    for (int step = 0; step < N_ - 1; step++) {
        int cur = cur_s;
        if (tid < E_) q_s[tid] = qf_s[tid] + Qcb[(size_t)cur * E_ + tid];

        // prefetch first half of this thread's L2 M-segment (warps 8..15)
        float4 Mbuf[8];
        if (pL >= 2) {
#pragma unroll
            for (int i = 0; i < 8; i++) Mbuf[i] = MrowL2[i];
        }
        __syncthreads();

        // ---- attention: warps 0..7 = heads; lane l owns n = l+32j ----
        if (w < 8) {
            float a[4];
#pragma unroll
            for (int j = 0; j < 4; j++) {
                int n = l + 32 * j;
                float accs = 0.f;
#pragma unroll
                for (int jj = 0; jj < 8; jj++) {
                    float4 kv = *(const float4*)&k_s[n * KROW + w * 32 + jj * 4];
                    float4 qv = *(const float4*)&q_s[w * 32 + jj * 4];
                    accs = fmaf(kv.x, qv.x, accs); accs = fmaf(kv.y, qv.y, accs);
                    accs = fmaf(kv.z, qv.z, accs); accs = fmaf(kv.w, qv.w, accs);
                }
                accs *= SCALE_;
                if (vis_s[n]) accs = NEGV;
                a[j] = accs;
            }
            float m = fmaxf(fmaxf(a[0], a[1]), fmaxf(a[2], a[3]));
#pragma unroll
            for (int o = 16; o; o >>= 1) m = fmaxf(m, __shfl_xor_sync(0xffffffffu, m, o));
            float ssum = 0.f;
#pragma unroll
            for (int j = 0; j < 4; j++) { a[j] = expf(a[j] - m); ssum += a[j]; }
#pragma unroll
            for (int o = 16; o; o >>= 1) ssum += __shfl_xor_sync(0xffffffffu, ssum, o);
            float inv = 1.0f / ssum;
#pragma unroll
            for (int j = 0; j < 4; j++) {
                int n = l + 32 * j;
                attn_s[w * 130 + n + (j >> 1)] = a[j] * inv;  // pad after n>=64
            }
        }
        __syncthreads();

        // ---- ctx[d] = sum_n attn[h(d)][n] * v[n][d]  (v in regs) ----
        {
            int d = tid >> 1, nh = tid & 1, hh = d >> 5;
            const float* ap = attn_s + hh * 130 + nh * 65;
            float acc = 0.f;
#pragma unroll
            for (int i = 0; i < 64; i++) acc = fmaf(ap[i], v_reg[i], acc);
            acc += __shfl_xor_sync(0xffffffffu, acc, 1);
            if (!nh) ctx_s[d] = acc;
        }
        __syncthreads();

        // ---- logits partials: thread (nL, pL) covers d in [64*pL, 64*pL+64) ----
        {
            const float4* c4 = (const float4*)ctx_s + pL * 16;
            float acc = 0.f;
            if (pL < 2) {
                const float4* mr = Ms4 + nL * MSU + pL * 16;
#pragma unroll
                for (int i = 0; i < 16; i++) {
                    float4 m = mr[i], c = c4[i];
                    acc = fmaf(c.x, m.x, acc); acc = fmaf(c.y, m.y, acc);
                    acc = fmaf(c.z, m.z, acc); acc = fmaf(c.w, m.w, acc);
                }
            } else {
#pragma unroll
                for (int i = 0; i < 8; i++) {
                    float4 m = Mbuf[i], c = c4[i];
                    acc = fmaf(c.x, m.x, acc); acc = fmaf(c.y, m.y, acc);
                    acc = fmaf(c.z, m.z, acc); acc = fmaf(c.w, m.w, acc);
                }
#pragma unroll
                for (int i = 8; i < 16; i++) {
                    float4 m = MrowL2[i], c = c4[i];
                    acc = fmaf(c.x, m.x, acc); acc = fmaf(c.y, m.y, acc);
                    acc = fmaf(c.z, m.z, acc); acc = fmaf(c.w, m.w, acc);
                }
            }
            lp_part[pL][nL] = acc;
        }
        __syncthreads();

        // ---- finalize logits ----
        if (tid < N_) {
            float s = lp_part[0][tid] + lp_part[1][tid] + lp_part[2][tid] + lp_part[3][tid];
            float lg = tanhf(fmaf(SCALE_, s, bd_s[tid])) * CLIPV;
            if (vis_s[tid]) lg = NEGV;
            logits_s[tid] = lg;
        }
        __syncthreads();

        // ---- warp 0: argmax (first-index ties) + logsumexp + state update ----
        if (w == 0) {
            float lv[4];
            float bv = -3.0e38f; int bi = 0;
#pragma unroll
            for (int j = 0; j < 4; j++) {
                lv[j] = logits_s[l + 32 * j];
                if (lv[j] > bv) { bv = lv[j]; bi = l + 32 * j; }
            }
#pragma unroll
            for (int o = 16; o; o >>= 1) {
                float ov = __shfl_xor_sync(0xffffffffu, bv, o);
                int oi = __shfl_xor_sync(0xffffffffu, bi, o);
                if (ov > bv || (ov == bv && oi < bi)) { bv = ov; bi = oi; }
            }
            float es = 0.f;
#pragma unroll
            for (int j = 0; j < 4; j++) es += expf(lv[j] - bv);
#pragma unroll
            for (int o = 16; o; o >>= 1) es += __shfl_xor_sync(0xffffffffu, es, o);
            if (l == 0) {
                lp -= logf(es);
                cur_s = bi;
                vis_s[bi] = 1;
            }
        }
        __syncthreads();
    }

    if (tid == 0) out[b] = lp;
}

// ---------------- host launch ----------------
extern "C" void kernel_launch(void* const* d_in, const int* in_sizes, int n_in,
                              void* d_out, int out_size) {
    const float* ne    = (const float*)d_in[0];
    const float* Wqkv  = (const float*)d_in[1];
    const float* bqkv  = (const float*)d_in[2];
    const float* Wfix  = (const float*)d_in[3];
    const float* bfix  = (const float*)d_in[4];
    const float* Wstep = (const float*)d_in[5];
    const float* bstep = (const float*)d_in[6];
    const float* Wmlp  = (const float*)d_in[7];
    const float* bmlp  = (const float*)d_in[8];
    float* out = (float*)d_out;

    float *p_qkv = nullptr, *p_Qc = nullptr, *p_M = nullptr;
    cudaGetSymbolAddress((void**)&p_qkv, g_qkv);
    cudaGetSymbolAddress((void**)&p_Qc, g_Qc);
    cudaGetSymbolAddress((void**)&p_M, g_M);

    size_t dec_smem = (size_t)N_ * KROW * sizeof(float)        // k: 133120
                    + (size_t)N_ * MSU * sizeof(float4);       // Ms: 67584
    cudaFuncSetAttribute(decode_k, cudaFuncAttributeMaxDynamicSharedMemorySize,
                         (int)dec_smem);

    mean_k<<<B_, E_>>>(ne);
    qfirst_k<<<B_, E_>>>(ne, Wfix, bfix, Wstep, bstep);

    sgemm_k<0><<<dim3(768 / 128, (B_ * N_) / 128), 256>>>(ne, Wqkv, bqkv, p_qkv,
                                                          E_, E_, 768, 768);
    sgemm_k<0><<<dim3(E_ / 128, (B_ * N_) / 128), 256>>>(ne, Wstep + 256 * 256, nullptr,
                                                         p_Qc, E_, E_, E_, E_);
    sgemm_k<1><<<dim3(E_ / 128, (B_ * N_) / 128), 256>>>(p_qkv + 512, Wmlp, nullptr,
                                                         p_M, E_, 768, E_, E_);
    bdot_k<<<(B_ * N_) / 8, 256>>>(bmlp);

    decode_k<<<B_, 512, dec_smem>>>(out);
}

// round 4
// speedup vs baseline: 1.5804x; 1.5069x over previous
#include <cuda_runtime.h>
#include <math.h>

#define B_ 512
#define N_ 128
#define E_ 256
#define H_ 8
#define D_ 32
#define SCALE_ 0.17677669529663687f  /* 1/sqrt(32) */
#define NEGV  (-1000000000.0f)
#define CLIPV 10.0f
#define MTU   129                    /* Ms4T row stride in float4 units */

// ---------------- scratch (device globals; no allocation) ----------------
__device__ float g_qkv[(size_t)B_ * N_ * 768];   // k | v | logit_k
__device__ float g_Qc [(size_t)B_ * N_ * E_];    // X @ Wstep_bot
__device__ float g_M  [(size_t)B_ * N_ * E_];    // logit_k @ Wmlp^T
__device__ float g_P  [(size_t)B_ * N_ * 1024];  // precomputed attn logits [b][i][h][n]
__device__ float g_bdot[B_ * N_];
__device__ float g_ge [B_ * E_];
__device__ float g_qf [B_ * E_];

// ---------------- graph_emb = mean over nodes ----------------
__global__ void mean_k(const float* __restrict__ ne) {
    int b = blockIdx.x, e = threadIdx.x;
    const float* p = ne + (size_t)b * N_ * E_ + e;
    float s = 0.f;
#pragma unroll 8
    for (int n = 0; n < N_; n++) s += p[(size_t)n * E_];
    g_ge[b * E_ + e] = s * (1.0f / N_);
}

// ---------------- q_first = ge@Wfix + first@Wstep_top + bfix + bstep ----------------
__global__ void qfirst_k(const float* __restrict__ ne,
                         const float* __restrict__ Wfix, const float* __restrict__ bfix,
                         const float* __restrict__ Wstep, const float* __restrict__ bstep) {
    __shared__ float ge_s[E_], fi_s[E_];
    int b = blockIdx.x, t = threadIdx.x;
    ge_s[t] = g_ge[b * E_ + t];
    fi_s[t] = ne[(size_t)b * N_ * E_ + t];
    __syncthreads();
    float acc = bfix[t] + bstep[t];
#pragma unroll 4
    for (int f = 0; f < E_; f++) {
        acc = fmaf(ge_s[f], Wfix[f * E_ + t], acc);
        acc = fmaf(fi_s[f], Wstep[f * E_ + t], acc);
    }
    g_qf[b * E_ + t] = acc;
}

// ---------------- generic fp32 GEMM: C = A(MxK)*B(KxN) [+bias] ----------------
template <int TRANSB>
__global__ void __launch_bounds__(256) sgemm_k(
    const float* __restrict__ A, const float* __restrict__ Bm,
    const float* __restrict__ bias, float* __restrict__ C,
    int K, int lda, int ldb, int ldc) {
    __shared__ float As[8][128];
    __shared__ float Bs[8][128];
    int tid = threadIdx.x;
    int tx = tid & 15, ty = tid >> 4;
    int rowBase = blockIdx.y * 128;
    int colBase = blockIdx.x * 128;

    float acc[8][8];
#pragma unroll
    for (int i = 0; i < 8; i++)
#pragma unroll
        for (int j = 0; j < 8; j++) acc[i][j] = 0.f;

    int aR = tid >> 1;
    int aC = (tid & 1) * 4;
    int bK_n = tid >> 5;
    int bC_n = (tid & 31) * 4;
    int bCol_t = tid & 127;
    int bK_t = (tid >> 7) * 4;

    for (int kt = 0; kt < K; kt += 8) {
        float4 av = *(const float4*)(A + (size_t)(rowBase + aR) * lda + kt + aC);
        As[aC + 0][aR] = av.x; As[aC + 1][aR] = av.y;
        As[aC + 2][aR] = av.z; As[aC + 3][aR] = av.w;
        if (!TRANSB) {
            float4 bv = *(const float4*)(Bm + (size_t)(kt + bK_n) * ldb + colBase + bC_n);
            *(float4*)&Bs[bK_n][bC_n] = bv;
        } else {
            float4 bv = *(const float4*)(Bm + (size_t)(colBase + bCol_t) * ldb + kt + bK_t);
            Bs[bK_t + 0][bCol_t] = bv.x; Bs[bK_t + 1][bCol_t] = bv.y;
            Bs[bK_t + 2][bCol_t] = bv.z; Bs[bK_t + 3][bCol_t] = bv.w;
        }
        __syncthreads();
#pragma unroll
        for (int kk = 0; kk < 8; kk++) {
            float ra[8], rb[8];
            *(float4*)&ra[0] = *(const float4*)&As[kk][ty * 8];
            *(float4*)&ra[4] = *(const float4*)&As[kk][ty * 8 + 4];
            *(float4*)&rb[0] = *(const float4*)&Bs[kk][tx * 8];
            *(float4*)&rb[4] = *(const float4*)&Bs[kk][tx * 8 + 4];
#pragma unroll
            for (int i = 0; i < 8; i++)
#pragma unroll
                for (int j = 0; j < 8; j++) acc[i][j] = fmaf(ra[i], rb[j], acc[i][j]);
        }
        __syncthreads();
    }
#pragma unroll
    for (int i = 0; i < 8; i++) {
        int r = rowBase + ty * 8 + i;
#pragma unroll
        for (int j = 0; j < 8; j += 4) {
            int c = colBase + tx * 8 + j;
            float4 v;
            v.x = acc[i][j]; v.y = acc[i][j + 1]; v.z = acc[i][j + 2]; v.w = acc[i][j + 3];
            if (bias) { v.x += bias[c]; v.y += bias[c + 1]; v.z += bias[c + 2]; v.w += bias[c + 3]; }
            *(float4*)(C + (size_t)r * ldc + c) = v;
        }
    }
}

// ---------------- P[b][i][h][n] = SCALE * (qf[b]+Qc[b][i])_h . k[b][n]_h ----------------
__global__ void __launch_bounds__(256) pmat_k(float* __restrict__ P) {
    __shared__ float kt[32][132];   // [d][n]
    __shared__ float qt[32][132];
    int h = blockIdx.x & 7, b = blockIdx.x >> 3;
    int tid = threadIdx.x;
    const float* kb  = g_qkv + (size_t)b * N_ * 768 + h * 32;
    const float* qcb = g_Qc  + (size_t)b * N_ * 256 + h * 32;
    const float* qfb = g_qf  + b * 256 + h * 32;

    for (int idx = tid; idx < N_ * 8; idx += 256) {
        int n = idx >> 3, d4 = (idx & 7) * 4;
        float4 kv  = *(const float4*)(kb  + (size_t)n * 768 + d4);
        float4 qv  = *(const float4*)(qcb + (size_t)n * 256 + d4);
        float4 qf4 = *(const float4*)(qfb + d4);
        kt[d4 + 0][n] = kv.x; kt[d4 + 1][n] = kv.y;
        kt[d4 + 2][n] = kv.z; kt[d4 + 3][n] = kv.w;
        qt[d4 + 0][n] = qv.x + qf4.x; qt[d4 + 1][n] = qv.y + qf4.y;
        qt[d4 + 2][n] = qv.z + qf4.z; qt[d4 + 3][n] = qv.w + qf4.w;
    }
    __syncthreads();

    int tx = tid & 15, ty = tid >> 4;
    float acc[8][8];
#pragma unroll
    for (int i = 0; i < 8; i++)
#pragma unroll
        for (int j = 0; j < 8; j++) acc[i][j] = 0.f;

#pragma unroll 4
    for (int d = 0; d < 32; d++) {
        float ra[8], rb[8];
        *(float4*)&ra[0] = *(const float4*)&qt[d][ty * 8];
        *(float4*)&ra[4] = *(const float4*)&qt[d][ty * 8 + 4];
        *(float4*)&rb[0] = *(const float4*)&kt[d][tx * 8];
        *(float4*)&rb[4] = *(const float4*)&kt[d][tx * 8 + 4];
#pragma unroll
        for (int i = 0; i < 8; i++)
#pragma unroll
            for (int j = 0; j < 8; j++) acc[i][j] = fmaf(ra[i], rb[j], acc[i][j]);
    }

#pragma unroll
    for (int i = 0; i < 8; i++) {
        float* row = P + ((size_t)(b * N_ + ty * 8 + i)) * 1024 + h * 128 + tx * 8;
#pragma unroll
        for (int j = 0; j < 8; j += 4) {
            float4 v;
            v.x = acc[i][j] * SCALE_;     v.y = acc[i][j + 1] * SCALE_;
            v.z = acc[i][j + 2] * SCALE_; v.w = acc[i][j + 3] * SCALE_;
            *(float4*)(row + j) = v;
        }
    }
}

// ---------------- bdot[row] = SCALE * (bmlp . logit_k[row]) ----------------
__global__ void bdot_k(const float* __restrict__ bmlp) {
    int w = threadIdx.x >> 5, l = threadIdx.x & 31;
    int row = blockIdx.x * 8 + w;
    const float* lk = g_qkv + (size_t)row * 768 + 512;
    float acc = 0.f;
#pragma unroll
    for (int j = 0; j < 8; j++) acc = fmaf(bmlp[l + 32 * j], lk[l + 32 * j], acc);
#pragma unroll
    for (int o = 16; o; o >>= 1) acc += __shfl_xor_sync(0xffffffffu, acc, o);
    if (l == 0) g_bdot[row] = acc * SCALE_;
}

// ---------------- sequential greedy decode: 1 CTA (512 thr) per batch ----------------
// Per-step global traffic: one 4 KB P row. M fully in smem (transposed,
// conflict-free); v in registers. No q/k work in the loop at all.
__global__ void __launch_bounds__(512, 1) decode_k(float* __restrict__ out) {
    extern __shared__ float dyn_s[];
    float4* Ms4T = (float4*)dyn_s;                   // [64 u][MTU], n contiguous

    __shared__ float attn_s[H_ * 132];               // [h][n], +4 pad at n>=64
    __shared__ float ctx_s[E_];
    __shared__ float lp_part[4][N_];
    __shared__ float logits_s[N_], bd_s[N_];
    __shared__ int cur_s;
    __shared__ unsigned char vis_s[N_];

    int b = blockIdx.x, tid = threadIdx.x;
    int w = tid >> 5, l = tid & 31;

    const float* kbase = g_qkv + (size_t)b * N_ * 768;
    const float4* Mb4 = (const float4*)(g_M + (size_t)b * N_ * E_);
    const float4* Pb = (const float4*)(g_P + (size_t)b * N_ * 1024);

    // stage M transposed: Ms4T[u][n] = M[n][u]  (one-time; STS conflicts OK)
    for (int idx = tid; idx < N_ * 64; idx += 512) {
        int n = idx >> 6, u = idx & 63;
        Ms4T[u * MTU + n] = Mb4[n * 64 + u];
    }
    // stage v into registers: thread t holds v[nh*64+i][d], d=t>>1, nh=t&1
    float v_reg[64];
    {
        int d = tid >> 1, nh = tid & 1;
        const float* vb = kbase + 256 + d + (size_t)nh * 64 * 768;
#pragma unroll
        for (int i = 0; i < 64; i++) v_reg[i] = vb[(size_t)i * 768];
    }
    if (tid < N_) {
        bd_s[tid] = g_bdot[b * N_ + tid];
        vis_s[tid] = (tid == 0) ? 1 : 0;
    }
    if (tid == 0) cur_s = 0;
    __syncthreads();

    int nL = tid & 127, pL = tid >> 7;
    float lp = 0.f;

    for (int step = 0; step < N_ - 1; step++) {
        int cur = cur_s;

        // ---- A: warps 0..7 = heads; lane l owns n = 4l..4l+3 (P row lookup) ----
        if (w < 8) {
            float4 pv = Pb[(size_t)cur * 256 + w * 32 + l];
            int n0 = 4 * l;
            float a0 = vis_s[n0 + 0] ? NEGV : pv.x;
            float a1 = vis_s[n0 + 1] ? NEGV : pv.y;
            float a2 = vis_s[n0 + 2] ? NEGV : pv.z;
            float a3 = vis_s[n0 + 3] ? NEGV : pv.w;
            float m = fmaxf(fmaxf(a0, a1), fmaxf(a2, a3));
#pragma unroll
            for (int o = 16; o; o >>= 1) m = fmaxf(m, __shfl_xor_sync(0xffffffffu, m, o));
            a0 = expf(a0 - m); a1 = expf(a1 - m); a2 = expf(a2 - m); a3 = expf(a3 - m);
            float ssum = a0 + a1 + a2 + a3;
#pragma unroll
            for (int o = 16; o; o >>= 1) ssum += __shfl_xor_sync(0xffffffffu, ssum, o);
            float inv = 1.0f / ssum;
            float4 wv;
            wv.x = a0 * inv; wv.y = a1 * inv; wv.z = a2 * inv; wv.w = a3 * inv;
            *(float4*)&attn_s[w * 132 + n0 + 4 * (l >= 16)] = wv;
        }
        __syncthreads();

        // ---- B: ctx[d] = sum_n attn[h(d)][n] * v[n][d]  (v in regs) ----
        {
            int d = tid >> 1, nh = tid & 1, hh = d >> 5;
            const float* ap = attn_s + hh * 132 + nh * 68;
            float acc = 0.f;
#pragma unroll
            for (int i = 0; i < 64; i++) acc = fmaf(ap[i], v_reg[i], acc);
            acc += __shfl_xor_sync(0xffffffffu, acc, 1);
            if (!nh) ctx_s[d] = acc;
        }
        __syncthreads();

        // ---- C: logits partials: thread (nL,pL) covers d-units [16*pL,16*pL+16) ----
        {
            const float4* c4 = (const float4*)ctx_s + pL * 16;
            const float4* mr = Ms4T + (pL * 16) * MTU + nL;
            float acc = 0.f;
#pragma unroll
            for (int i = 0; i < 16; i++) {
                float4 m = mr[i * MTU], c = c4[i];
                acc = fmaf(c.x, m.x, acc); acc = fmaf(c.y, m.y, acc);
                acc = fmaf(c.z, m.z, acc); acc = fmaf(c.w, m.w, acc);
            }
            lp_part[pL][nL] = acc;
        }
        __syncthreads();

        // ---- D: finalize logits ----
        if (tid < N_) {
            float s = lp_part[0][tid] + lp_part[1][tid] + lp_part[2][tid] + lp_part[3][tid];
            float lg = tanhf(fmaf(SCALE_, s, bd_s[tid])) * CLIPV;
            if (vis_s[tid]) lg = NEGV;
            logits_s[tid] = lg;
        }
        __syncthreads();

        // ---- E: warp 0: argmax (first-index ties) + logsumexp + state update ----
        if (w == 0) {
            float lv[4];
            float bv = -3.0e38f; int bi = 0;
#pragma unroll
            for (int j = 0; j < 4; j++) {
                lv[j] = logits_s[l + 32 * j];
                if (lv[j] > bv) { bv = lv[j]; bi = l + 32 * j; }
            }
#pragma unroll
            for (int o = 16; o; o >>= 1) {
                float ov = __shfl_xor_sync(0xffffffffu, bv, o);
                int oi = __shfl_xor_sync(0xffffffffu, bi, o);
                if (ov > bv || (ov == bv && oi < bi)) { bv = ov; bi = oi; }
            }
            float es = 0.f;
#pragma unroll
            for (int j = 0; j < 4; j++) es += expf(lv[j] - bv);
#pragma unroll
            for (int o = 16; o; o >>= 1) es += __shfl_xor_sync(0xffffffffu, es, o);
            if (l == 0) {
                lp -= logf(es);
                cur_s = bi;
                vis_s[bi] = 1;
            }
        }
        __syncthreads();
    }

    if (tid == 0) out[b] = lp;
}

// ---------------- host launch ----------------
extern "C" void kernel_launch(void* const* d_in, const int* in_sizes, int n_in,
                              void* d_out, int out_size) {
    const float* ne    = (const float*)d_in[0];
    const float* Wqkv  = (const float*)d_in[1];
    const float* bqkv  = (const float*)d_in[2];
    const float* Wfix  = (const float*)d_in[3];
    const float* bfix  = (const float*)d_in[4];
    const float* Wstep = (const float*)d_in[5];
    const float* bstep = (const float*)d_in[6];
    const float* Wmlp  = (const float*)d_in[7];
    const float* bmlp  = (const float*)d_in[8];
    float* out = (float*)d_out;

    float *p_qkv = nullptr, *p_Qc = nullptr, *p_M = nullptr, *p_P = nullptr;
    cudaGetSymbolAddress((void**)&p_qkv, g_qkv);
    cudaGetSymbolAddress((void**)&p_Qc, g_Qc);
    cudaGetSymbolAddress((void**)&p_M, g_M);
    cudaGetSymbolAddress((void**)&p_P, g_P);

    size_t dec_smem = (size_t)64 * MTU * sizeof(float4);   // 132096
    cudaFuncSetAttribute(decode_k, cudaFuncAttributeMaxDynamicSharedMemorySize,
                         (int)dec_smem);

    mean_k<<<B_, E_>>>(ne);
    qfirst_k<<<B_, E_>>>(ne, Wfix, bfix, Wstep, bstep);

    sgemm_k<0><<<dim3(768 / 128, (B_ * N_) / 128), 256>>>(ne, Wqkv, bqkv, p_qkv,
                                                          E_, E_, 768, 768);
    sgemm_k<0><<<dim3(E_ / 128, (B_ * N_) / 128), 256>>>(ne, Wstep + 256 * 256, nullptr,
                                                         p_Qc, E_, E_, E_, E_);
    sgemm_k<1><<<dim3(E_ / 128, (B_ * N_) / 128), 256>>>(p_qkv + 512, Wmlp, nullptr,
                                                         p_M, E_, 768, E_, E_);
    pmat_k<<<B_ * H_, 256>>>(p_P);
    bdot_k<<<(B_ * N_) / 8, 256>>>(bmlp);

    decode_k<<<B_, 512, dec_smem>>>(out);
}